// round 1
// baseline (speedup 1.0000x reference)
#include <cuda_runtime.h>
#include <math.h>

// Problem constants
#define BATCH 256
#define TDIM  80
#define CDIM  512
#define HDIM  512
#define NCLS  6625
#define SLEN  25
#define XW    (CDIM + NCLS)   // 7137, gru_wih row stride

// Scratch (device globals; no allocation allowed)
__device__ float g_proj[BATCH * TDIM * HDIM];   // [B,T,H] i2h projection (~42 MB)
__device__ float g_h   [BATCH * HDIM];          // GRU hidden state
__device__ float g_prev[BATCH * HDIM];          // h @ h2h_w.T + b
__device__ float g_ctx [BATCH * CDIM];          // attention context
__device__ float g_gi  [BATCH * 3 * HDIM];      // ctx @ wih[:, :C].T
__device__ float g_gh  [BATCH * 3 * HDIM];      // h   @ whh.T
__device__ float g_hid [BATCH * SLEN * HDIM];   // all hidden states [B,S,H]

// ---------------------------------------------------------------------------
// Generic fp32 GEMM: C[M,N] = A[M,K] * B[N,K]^T (+ bias[N])
// A row-major lda, B row-major ldb (K contiguous in both), C row-major ldc.
// 64x64 tile, BK=16, 256 threads, 4x4 per-thread register tile.
// K must be a multiple of 16 (all our K = 512).
// ---------------------------------------------------------------------------
__global__ __launch_bounds__(256) void sgemm_nt(
    const float* __restrict__ A, int lda,
    const float* __restrict__ B, int ldb,
    float* __restrict__ C, int ldc,
    const float* __restrict__ bias,
    int M, int N, int K)
{
    __shared__ float As[64][17];
    __shared__ float Bs[64][17];

    const int tid = threadIdx.x;
    const int tx = tid & 15;       // 0..15  (N direction)
    const int ty = tid >> 4;       // 0..15  (M direction)
    const int row0 = blockIdx.y * 64;
    const int col0 = blockIdx.x * 64;

    float acc[4][4] = {};

    for (int k0 = 0; k0 < K; k0 += 16) {
        #pragma unroll
        for (int l = 0; l < 4; l++) {
            int idx = tid + l * 256;         // 0..1023
            int r  = idx >> 4;               // 0..63
            int kk = idx & 15;               // 0..15
            int ar = row0 + r;
            As[r][kk] = (ar < M) ? A[(size_t)ar * lda + k0 + kk] : 0.0f;
            int br = col0 + r;
            Bs[r][kk] = (br < N) ? B[(size_t)br * ldb + k0 + kk] : 0.0f;
        }
        __syncthreads();

        #pragma unroll
        for (int kk = 0; kk < 16; kk++) {
            float a[4], b[4];
            #pragma unroll
            for (int i = 0; i < 4; i++) a[i] = As[ty * 4 + i][kk];
            #pragma unroll
            for (int j = 0; j < 4; j++) b[j] = Bs[tx * 4 + j][kk];
            #pragma unroll
            for (int i = 0; i < 4; i++)
                #pragma unroll
                for (int j = 0; j < 4; j++)
                    acc[i][j] += a[i] * b[j];
        }
        __syncthreads();
    }

    #pragma unroll
    for (int i = 0; i < 4; i++) {
        int row = row0 + ty * 4 + i;
        if (row >= M) continue;
        #pragma unroll
        for (int j = 0; j < 4; j++) {
            int col = col0 + tx * 4 + j;
            if (col < N) {
                float v = acc[i][j];
                if (bias) v += bias[col];
                C[(size_t)row * ldc + col] = v;
            }
        }
    }
}

// ---------------------------------------------------------------------------
// Zero the hidden state
// ---------------------------------------------------------------------------
__global__ void zero_h_kernel()
{
    g_h[blockIdx.x * HDIM + threadIdx.x] = 0.0f;
}

// ---------------------------------------------------------------------------
// Attention: per batch element b (one CTA, 512 threads = 16 warps)
//   e[t]     = sum_h tanh(proj[b,t,h] + prev[b,h]) * score_w[h]
//   alpha    = softmax(e)
//   ctx[b,c] = sum_t alpha[t] * inputs[b,t,c]
// ---------------------------------------------------------------------------
__global__ __launch_bounds__(512) void attn_kernel(
    const float* __restrict__ inputs,
    const float* __restrict__ score_w)
{
    const int b    = blockIdx.x;
    const int tid  = threadIdx.x;
    const int lane = tid & 31;
    const int wid  = tid >> 5;   // 0..15

    __shared__ float prevs[HDIM];
    __shared__ float sw[HDIM];
    __shared__ float e[TDIM];
    __shared__ float red[2];

    prevs[tid] = g_prev[b * HDIM + tid];
    sw[tid]    = score_w[tid];
    __syncthreads();

    const float* projb = g_proj + (size_t)b * TDIM * HDIM;

    // Phase 1: scores (warp w handles t = w, w+16, ...)
    for (int t = wid; t < TDIM; t += 16) {
        const float* p = projb + t * HDIM;
        float part = 0.0f;
        #pragma unroll 4
        for (int h = lane; h < HDIM; h += 32)
            part += tanhf(p[h] + prevs[h]) * sw[h];
        #pragma unroll
        for (int off = 16; off; off >>= 1)
            part += __shfl_down_sync(0xffffffffu, part, off);
        if (lane == 0) e[t] = part;
    }
    __syncthreads();

    // Phase 2: softmax over T=80 (cheap, serialized on thread 0)
    if (tid == 0) {
        float m = -1e30f;
        for (int t = 0; t < TDIM; t++) m = fmaxf(m, e[t]);
        red[0] = m;
    }
    __syncthreads();
    if (tid < TDIM) e[tid] = expf(e[tid] - red[0]);
    __syncthreads();
    if (tid == 0) {
        float s = 0.0f;
        for (int t = 0; t < TDIM; t++) s += e[t];
        red[1] = 1.0f / s;
    }
    __syncthreads();

    // Phase 3: context (thread c accumulates over t)
    const float inv = red[1];
    const float* inb = inputs + (size_t)b * TDIM * CDIM;
    float acc = 0.0f;
    #pragma unroll 4
    for (int t = 0; t < TDIM; t++)
        acc += e[t] * inb[t * CDIM + tid];
    g_ctx[b * CDIM + tid] = acc * inv;
}

// ---------------------------------------------------------------------------
// GRU gates. One CTA per b, 512 threads (thread k = hidden unit).
// The one-hot contribution to gi is a single column gather of gru_wih.
// ---------------------------------------------------------------------------
__global__ __launch_bounds__(512) void gru_gate_kernel(
    const int*   __restrict__ targets,
    const float* __restrict__ wih,
    const float* __restrict__ bih,
    const float* __restrict__ bhh,
    int s)
{
    const int b = blockIdx.x;
    const int k = threadIdx.x;

    const int tgt = targets[b * SLEN + s];
    const size_t ocol = (size_t)CDIM + tgt;

    const float* gi = g_gi + b * 3 * HDIM;
    const float* gh = g_gh + b * 3 * HDIM;

    float ir = gi[k]            + bih[k]            + wih[(size_t)k * XW + ocol];
    float iz = gi[HDIM + k]     + bih[HDIM + k]     + wih[(size_t)(HDIM + k) * XW + ocol];
    float in = gi[2 * HDIM + k] + bih[2 * HDIM + k] + wih[(size_t)(2 * HDIM + k) * XW + ocol];
    float hr = gh[k]            + bhh[k];
    float hz = gh[HDIM + k]     + bhh[HDIM + k];
    float hn = gh[2 * HDIM + k] + bhh[2 * HDIM + k];

    float r = 1.0f / (1.0f + expf(-(ir + hr)));
    float z = 1.0f / (1.0f + expf(-(iz + hz)));
    float n = tanhf(in + r * hn);

    float hp   = g_h[b * HDIM + k];
    float hnew = (1.0f - z) * n + z * hp;

    g_h[b * HDIM + k] = hnew;
    g_hid[((size_t)b * SLEN + s) * HDIM + k] = hnew;
}

// ---------------------------------------------------------------------------
// Launch
// ---------------------------------------------------------------------------
extern "C" void kernel_launch(void* const* d_in, const int* in_sizes, int n_in,
                              void* d_out, int out_size)
{
    const float* inputs  = (const float*)d_in[0];
    const int*   targets = (const int*)  d_in[1];
    int o = (in_sizes[2] == 1) ? 3 : 2;   // skip batch_max_length scalar if present
    const float* i2h_w   = (const float*)d_in[o + 0];
    const float* h2h_w   = (const float*)d_in[o + 1];
    const float* h2h_b   = (const float*)d_in[o + 2];
    const float* score_w = (const float*)d_in[o + 3];
    const float* gru_wih = (const float*)d_in[o + 4];
    const float* gru_whh = (const float*)d_in[o + 5];
    const float* gru_bih = (const float*)d_in[o + 6];
    const float* gru_bhh = (const float*)d_in[o + 7];
    const float* gen_w   = (const float*)d_in[o + 8];
    const float* gen_b   = (const float*)d_in[o + 9];
    float* out = (float*)d_out;

    static float *p_proj = nullptr, *p_h, *p_prev, *p_ctx, *p_gi, *p_gh, *p_hid;
    if (!p_proj) {
        cudaGetSymbolAddress((void**)&p_proj, g_proj);
        cudaGetSymbolAddress((void**)&p_h,    g_h);
        cudaGetSymbolAddress((void**)&p_prev, g_prev);
        cudaGetSymbolAddress((void**)&p_ctx,  g_ctx);
        cudaGetSymbolAddress((void**)&p_gi,   g_gi);
        cudaGetSymbolAddress((void**)&p_gh,   g_gh);
        cudaGetSymbolAddress((void**)&p_hid,  g_hid);
    }

    // h0 = 0
    zero_h_kernel<<<BATCH, HDIM>>>();

    // batch_H_proj = inputs @ i2h_w.T   [20480, 512]
    sgemm_nt<<<dim3(HDIM / 64, (BATCH * TDIM) / 64), 256>>>(
        inputs, CDIM, i2h_w, CDIM, p_proj, HDIM, nullptr,
        BATCH * TDIM, HDIM, CDIM);

    for (int s = 0; s < SLEN; s++) {
        // prev = h @ h2h_w.T + h2h_b   [256, 512]
        sgemm_nt<<<dim3(HDIM / 64, BATCH / 64), 256>>>(
            p_h, HDIM, h2h_w, HDIM, p_prev, HDIM, h2h_b,
            BATCH, HDIM, HDIM);

        // attention -> g_ctx
        attn_kernel<<<BATCH, 512>>>(inputs, score_w);

        // gi = ctx @ wih[:, :C].T   [256, 1536]   (ldb = 7137)
        sgemm_nt<<<dim3((3 * HDIM) / 64, BATCH / 64), 256>>>(
            p_ctx, CDIM, gru_wih, XW, p_gi, 3 * HDIM, nullptr,
            BATCH, 3 * HDIM, CDIM);

        // gh = h @ whh.T   [256, 1536]
        sgemm_nt<<<dim3((3 * HDIM) / 64, BATCH / 64), 256>>>(
            p_h, HDIM, gru_whh, HDIM, p_gh, 3 * HDIM, nullptr,
            BATCH, 3 * HDIM, HDIM);

        // gates (one-hot gather + biases + nonlinearities), writes h and hiddens
        gru_gate_kernel<<<BATCH, HDIM>>>(targets, gru_wih, gru_bih, gru_bhh, s);
    }

    // probs = hiddens @ gen_w.T + gen_b   [6400, 6625]
    sgemm_nt<<<dim3((NCLS + 63) / 64, (BATCH * SLEN) / 64), 256>>>(
        p_hid, HDIM, gen_w, HDIM, out, NCLS, gen_b,
        BATCH * SLEN, NCLS, HDIM);
}

// round 2
// speedup vs baseline: 1.5792x; 1.5792x over previous
#include <cuda_runtime.h>
#include <math.h>
#include <stdint.h>

// Problem constants
#define BATCH 256
#define TDIM  80
#define CDIM  512
#define HDIM  512
#define NCLS  6625
#define SLEN  25
#define XW    (CDIM + NCLS)   // 7137, gru_wih row stride

// Scratch (device globals; no allocation allowed)
__device__ float g_proj[BATCH * TDIM * HDIM];   // [B,T,H] i2h projection (~42 MB)
__device__ float g_h   [BATCH * HDIM];          // GRU hidden state
__device__ float g_pg  [BATCH * 2048];          // fused [prev(512) | gh(1536)]
__device__ float g_ctx [BATCH * CDIM];          // attention context
__device__ float g_gi  [BATCH * 3 * HDIM];      // ctx @ wih[:, :C].T
__device__ float g_hid [BATCH * SLEN * HDIM];   // all hidden states [B,S,H]
__device__ float g_wcat[2048 * HDIM];           // [h2h_w ; gru_whh] concat
__device__ float g_bcat[2048];                  // [h2h_b ; zeros]

// ---------------------------------------------------------------------------
// tf32 helpers: 3-way split mma (hi*hi + hi*lo + lo*hi) ~ fp32 accuracy
// ---------------------------------------------------------------------------
__device__ __forceinline__ uint32_t f2tf32(float x) {
    uint32_t r;
    asm("cvt.rna.tf32.f32 %0, %1;" : "=r"(r) : "f"(x));
    return r;
}
__device__ __forceinline__ void split_tf32(float v, uint32_t& hi, uint32_t& lo) {
    hi = f2tf32(v);
    lo = f2tf32(v - __uint_as_float(hi));
}
__device__ __forceinline__ void mma_tf32(float* d, const uint32_t* a, const uint32_t* b) {
    asm volatile(
        "mma.sync.aligned.m16n8k8.row.col.f32.tf32.tf32.f32 "
        "{%0,%1,%2,%3}, {%4,%5,%6,%7}, {%8,%9}, {%0,%1,%2,%3};"
        : "+f"(d[0]), "+f"(d[1]), "+f"(d[2]), "+f"(d[3])
        : "r"(a[0]), "r"(a[1]), "r"(a[2]), "r"(a[3]),
          "r"(b[0]), "r"(b[1]));
}

// ---------------------------------------------------------------------------
// Tensor-core GEMM: C[M,N] = A[M,K] * B[N,K]^T (+ bias[N])
// A row-major lda, B row-major ldb. BK=16. tf32 3-split for fp32 accuracy.
// ---------------------------------------------------------------------------
#define TBK  16
#define TBKP 20   // padded smem k-stride (float4-aligned, conflict-free frag reads)

template<int BM, int BN, int WARPS_M, int WARPS_N, bool VEC>
__global__ __launch_bounds__(WARPS_M * WARPS_N * 32) void tgemm(
    const float* __restrict__ A, int lda,
    const float* __restrict__ B, int ldb,
    float* __restrict__ C, int ldc,
    const float* __restrict__ bias,
    int M, int N, int K)
{
    constexpr int THREADS = WARPS_M * WARPS_N * 32;
    constexpr int WM = BM / WARPS_M;
    constexpr int WN = BN / WARPS_N;
    constexpr int MT = WM / 16;
    constexpr int NT = WN / 8;

    __shared__ float As[BM][TBKP];
    __shared__ float Bs[BN][TBKP];

    const int tid  = threadIdx.x;
    const int wid  = tid >> 5;
    const int lane = tid & 31;
    const int g    = lane >> 2;   // group id 0..7
    const int t    = lane & 3;    // thread in group 0..3
    const int wm   = (wid / WARPS_N) * WM;
    const int wn   = (wid % WARPS_N) * WN;
    const int row0 = blockIdx.y * BM;
    const int col0 = blockIdx.x * BN;

    float acc[MT][NT][4];
    #pragma unroll
    for (int i = 0; i < MT; i++)
        #pragma unroll
        for (int j = 0; j < NT; j++)
            #pragma unroll
            for (int q = 0; q < 4; q++) acc[i][j][q] = 0.0f;

    for (int k0 = 0; k0 < K; k0 += TBK) {
        if (VEC) {
            #pragma unroll
            for (int l = 0; l < BM * 4 / THREADS; l++) {
                int idx = tid + l * THREADS;
                int r = idx >> 2, q = idx & 3;
                float4 v = make_float4(0.f, 0.f, 0.f, 0.f);
                if (row0 + r < M)
                    v = *(const float4*)(A + (size_t)(row0 + r) * lda + k0 + q * 4);
                *(float4*)&As[r][q * 4] = v;
            }
            #pragma unroll
            for (int l = 0; l < BN * 4 / THREADS; l++) {
                int idx = tid + l * THREADS;
                int r = idx >> 2, q = idx & 3;
                float4 v = make_float4(0.f, 0.f, 0.f, 0.f);
                if (col0 + r < N)
                    v = *(const float4*)(B + (size_t)(col0 + r) * ldb + k0 + q * 4);
                *(float4*)&Bs[r][q * 4] = v;
            }
        } else {
            #pragma unroll
            for (int l = 0; l < BM * TBK / THREADS; l++) {
                int idx = tid + l * THREADS;
                int r = idx >> 4, kk = idx & 15;
                As[r][kk] = (row0 + r < M) ? A[(size_t)(row0 + r) * lda + k0 + kk] : 0.0f;
            }
            #pragma unroll
            for (int l = 0; l < BN * TBK / THREADS; l++) {
                int idx = tid + l * THREADS;
                int r = idx >> 4, kk = idx & 15;
                Bs[r][kk] = (col0 + r < N) ? B[(size_t)(col0 + r) * ldb + k0 + kk] : 0.0f;
            }
        }
        __syncthreads();

        #pragma unroll
        for (int kk = 0; kk < TBK; kk += 8) {
            uint32_t ahi[MT][4], alo[MT][4];
            #pragma unroll
            for (int mt = 0; mt < MT; mt++) {
                int r0 = wm + mt * 16 + g;
                split_tf32(As[r0    ][kk + t    ], ahi[mt][0], alo[mt][0]);
                split_tf32(As[r0 + 8][kk + t    ], ahi[mt][1], alo[mt][1]);
                split_tf32(As[r0    ][kk + t + 4], ahi[mt][2], alo[mt][2]);
                split_tf32(As[r0 + 8][kk + t + 4], ahi[mt][3], alo[mt][3]);
            }
            uint32_t bhi[NT][2], blo[NT][2];
            #pragma unroll
            for (int nt = 0; nt < NT; nt++) {
                int c = wn + nt * 8 + g;
                split_tf32(Bs[c][kk + t    ], bhi[nt][0], blo[nt][0]);
                split_tf32(Bs[c][kk + t + 4], bhi[nt][1], blo[nt][1]);
            }
            #pragma unroll
            for (int mt = 0; mt < MT; mt++)
                #pragma unroll
                for (int nt = 0; nt < NT; nt++) {
                    mma_tf32(acc[mt][nt], ahi[mt], bhi[nt]);
                    mma_tf32(acc[mt][nt], ahi[mt], blo[nt]);
                    mma_tf32(acc[mt][nt], alo[mt], bhi[nt]);
                }
        }
        __syncthreads();
    }

    // Store: c0:(g,2t) c1:(g,2t+1) c2:(g+8,2t) c3:(g+8,2t+1)
    #pragma unroll
    for (int mt = 0; mt < MT; mt++) {
        int r = row0 + wm + mt * 16 + g;
        #pragma unroll
        for (int nt = 0; nt < NT; nt++) {
            int c = col0 + wn + nt * 8 + 2 * t;
            if (c >= N) continue;
            float* a4 = acc[mt][nt];
            float bb0 = bias ? bias[c] : 0.0f;
            float bb1 = (c + 1 < N) ? (bias ? bias[c + 1] : 0.0f) : 0.0f;
            if (r < M) {
                C[(size_t)r * ldc + c] = a4[0] + bb0;
                if (c + 1 < N) C[(size_t)r * ldc + c + 1] = a4[1] + bb1;
            }
            if (r + 8 < M) {
                C[(size_t)(r + 8) * ldc + c] = a4[2] + bb0;
                if (c + 1 < N) C[(size_t)(r + 8) * ldc + c + 1] = a4[3] + bb1;
            }
        }
    }
}

// ---------------------------------------------------------------------------
// Setup kernels (once per launch call)
// ---------------------------------------------------------------------------
__global__ void zero_h_kernel()
{
    g_h[blockIdx.x * HDIM + threadIdx.x] = 0.0f;
}

__global__ void build_wcat_kernel(const float* __restrict__ h2h_w,
                                  const float* __restrict__ whh)
{
    int n = blockIdx.x, k = threadIdx.x;
    g_wcat[n * HDIM + k] = (n < HDIM) ? h2h_w[n * HDIM + k]
                                      : whh[(n - HDIM) * HDIM + k];
}

__global__ void build_bcat_kernel(const float* __restrict__ h2h_b)
{
    int i = blockIdx.x * blockDim.x + threadIdx.x;
    g_bcat[i] = (i < HDIM) ? h2h_b[i] : 0.0f;
}

// ---------------------------------------------------------------------------
// Attention: one CTA per batch element (512 threads = 16 warps)
// prev now lives in g_pg[b][0:512] (stride 2048)
// ---------------------------------------------------------------------------
__global__ __launch_bounds__(512) void attn_kernel(
    const float* __restrict__ inputs,
    const float* __restrict__ score_w)
{
    const int b    = blockIdx.x;
    const int tid  = threadIdx.x;
    const int lane = tid & 31;
    const int wid  = tid >> 5;

    __shared__ float prevs[HDIM];
    __shared__ float sw[HDIM];
    __shared__ float e[TDIM];
    __shared__ float red[2];

    prevs[tid] = g_pg[b * 2048 + tid];
    sw[tid]    = score_w[tid];
    __syncthreads();

    const float* projb = g_proj + (size_t)b * TDIM * HDIM;

    for (int t = wid; t < TDIM; t += 16) {
        const float* p = projb + t * HDIM;
        float part = 0.0f;
        #pragma unroll 4
        for (int h = lane; h < HDIM; h += 32)
            part += tanhf(p[h] + prevs[h]) * sw[h];
        #pragma unroll
        for (int off = 16; off; off >>= 1)
            part += __shfl_down_sync(0xffffffffu, part, off);
        if (lane == 0) e[t] = part;
    }
    __syncthreads();

    if (tid == 0) {
        float m = -1e30f;
        for (int t = 0; t < TDIM; t++) m = fmaxf(m, e[t]);
        red[0] = m;
    }
    __syncthreads();
    if (tid < TDIM) e[tid] = expf(e[tid] - red[0]);
    __syncthreads();
    if (tid == 0) {
        float s = 0.0f;
        for (int t = 0; t < TDIM; t++) s += e[t];
        red[1] = 1.0f / s;
    }
    __syncthreads();

    const float inv = red[1];
    const float* inb = inputs + (size_t)b * TDIM * CDIM;
    float acc = 0.0f;
    #pragma unroll 4
    for (int t = 0; t < TDIM; t++)
        acc += e[t] * inb[t * CDIM + tid];
    g_ctx[b * CDIM + tid] = acc * inv;
}

// ---------------------------------------------------------------------------
// GRU gates: one CTA per b. gh lives in g_pg[b][512:2048].
// One-hot contribution = single column gather of gru_wih.
// ---------------------------------------------------------------------------
__global__ __launch_bounds__(512) void gru_gate_kernel(
    const int*   __restrict__ targets,
    const float* __restrict__ wih,
    const float* __restrict__ bih,
    const float* __restrict__ bhh,
    int s)
{
    const int b = blockIdx.x;
    const int k = threadIdx.x;

    const int tgt = targets[b * SLEN + s];
    const size_t ocol = (size_t)CDIM + tgt;

    const float* gi = g_gi + b * 3 * HDIM;
    const float* pg = g_pg + b * 2048;

    float ir = gi[k]            + bih[k]            + wih[(size_t)k * XW + ocol];
    float iz = gi[HDIM + k]     + bih[HDIM + k]     + wih[(size_t)(HDIM + k) * XW + ocol];
    float in = gi[2 * HDIM + k] + bih[2 * HDIM + k] + wih[(size_t)(2 * HDIM + k) * XW + ocol];
    float hr = pg[512 + k]            + bhh[k];
    float hz = pg[512 + HDIM + k]     + bhh[HDIM + k];
    float hn = pg[512 + 2 * HDIM + k] + bhh[2 * HDIM + k];

    float r = 1.0f / (1.0f + expf(-(ir + hr)));
    float z = 1.0f / (1.0f + expf(-(iz + hz)));
    float n = tanhf(in + r * hn);

    float hp   = g_h[b * HDIM + k];
    float hnew = (1.0f - z) * n + z * hp;

    g_h[b * HDIM + k] = hnew;
    g_hid[((size_t)b * SLEN + s) * HDIM + k] = hnew;
}

// ---------------------------------------------------------------------------
// Launch
// ---------------------------------------------------------------------------
extern "C" void kernel_launch(void* const* d_in, const int* in_sizes, int n_in,
                              void* d_out, int out_size)
{
    const float* inputs  = (const float*)d_in[0];
    const int*   targets = (const int*)  d_in[1];
    int o = (in_sizes[2] == 1) ? 3 : 2;   // skip batch_max_length scalar if present
    const float* i2h_w   = (const float*)d_in[o + 0];
    const float* h2h_w   = (const float*)d_in[o + 1];
    const float* h2h_b   = (const float*)d_in[o + 2];
    const float* score_w = (const float*)d_in[o + 3];
    const float* gru_wih = (const float*)d_in[o + 4];
    const float* gru_whh = (const float*)d_in[o + 5];
    const float* gru_bih = (const float*)d_in[o + 6];
    const float* gru_bhh = (const float*)d_in[o + 7];
    const float* gen_w   = (const float*)d_in[o + 8];
    const float* gen_b   = (const float*)d_in[o + 9];
    float* out = (float*)d_out;

    static float *p_proj = nullptr, *p_h, *p_pg, *p_ctx, *p_gi, *p_hid, *p_wcat, *p_bcat;
    if (!p_proj) {
        cudaGetSymbolAddress((void**)&p_proj, g_proj);
        cudaGetSymbolAddress((void**)&p_h,    g_h);
        cudaGetSymbolAddress((void**)&p_pg,   g_pg);
        cudaGetSymbolAddress((void**)&p_ctx,  g_ctx);
        cudaGetSymbolAddress((void**)&p_gi,   g_gi);
        cudaGetSymbolAddress((void**)&p_hid,  g_hid);
        cudaGetSymbolAddress((void**)&p_wcat, g_wcat);
        cudaGetSymbolAddress((void**)&p_bcat, g_bcat);
    }

    // setup
    zero_h_kernel<<<BATCH, HDIM>>>();
    build_wcat_kernel<<<2048, HDIM>>>(h2h_w, gru_whh);
    build_bcat_kernel<<<4, 512>>>(h2h_b);

    // batch_H_proj = inputs @ i2h_w.T   [20480, 512]
    tgemm<128, 128, 2, 4, true><<<dim3(HDIM / 128, (BATCH * TDIM) / 128), 256>>>(
        inputs, CDIM, i2h_w, CDIM, p_proj, HDIM, nullptr,
        BATCH * TDIM, HDIM, CDIM);

    for (int s = 0; s < SLEN; s++) {
        // fused: [prev | gh] = h @ [h2h_w ; gru_whh].T + [h2h_b ; 0]   [256, 2048]
        tgemm<64, 64, 2, 2, false><<<dim3(2048 / 64, BATCH / 64), 128>>>(
            p_h, HDIM, p_wcat, HDIM, p_pg, 2048, p_bcat,
            BATCH, 2048, HDIM);

        // attention -> g_ctx
        attn_kernel<<<BATCH, 512>>>(inputs, score_w);

        // gi = ctx @ wih[:, :C].T   [256, 1536]  (ldb = 7137, scalar loads)
        tgemm<64, 64, 2, 2, false><<<dim3((3 * HDIM) / 64, BATCH / 64), 128>>>(
            p_ctx, CDIM, gru_wih, XW, p_gi, 3 * HDIM, nullptr,
            BATCH, 3 * HDIM, CDIM);

        // gates (one-hot gather + biases + nonlinearities)
        gru_gate_kernel<<<BATCH, HDIM>>>(targets, gru_bih ? gru_wih : gru_wih,
                                         gru_bih, gru_bhh, s);
    }

    // probs = hiddens @ gen_w.T + gen_b   [6400, 6625]
    tgemm<128, 128, 2, 4, true><<<dim3((NCLS + 127) / 128, (BATCH * SLEN) / 128), 256>>>(
        p_hid, HDIM, gen_w, HDIM, out, NCLS, gen_b,
        BATCH * SLEN, NCLS, HDIM);
}